// round 15
// baseline (speedup 1.0000x reference)
#include <cuda_runtime.h>
#include <cuda_fp16.h>
#include <cstdint>

#define B_    2
#define S_    2048
#define D_    1024
#define H_    16
#define DH_   64
#define MTOT  (B_ * S_)

// fp16 scratch
__device__ __half g_q[(size_t)MTOT * D_];
__device__ __half g_k[(size_t)MTOT * D_];
__device__ __half g_v[(size_t)MTOT * D_];
__device__ __half g_o[(size_t)MTOT * D_];
__device__ __half g_xh[(size_t)MTOT * D_];
__device__ __half g_wh[4][(size_t)D_ * D_];

// ---------------------------------------------------------------------------
__device__ __forceinline__ uint32_t pack_h2(float lo, float hi) {
    uint32_t u;
    asm("cvt.rn.f16x2.f32 %0, %1, %2;" : "=r"(u) : "f"(hi), "f"(lo));
    return u;
}

__device__ __forceinline__ void mma_f16(float& c0, float& c1, float& c2, float& c3,
                                        uint32_t a0, uint32_t a1, uint32_t a2, uint32_t a3,
                                        uint32_t b0, uint32_t b1) {
    asm volatile(
        "mma.sync.aligned.m16n8k16.row.col.f32.f16.f16.f32 "
        "{%0,%1,%2,%3}, {%4,%5,%6,%7}, {%8,%9}, {%0,%1,%2,%3};"
        : "+f"(c0), "+f"(c1), "+f"(c2), "+f"(c3)
        : "r"(a0), "r"(a1), "r"(a2), "r"(a3), "r"(b0), "r"(b1));
}

__device__ __forceinline__ void cp_async16(uint32_t saddr, const void* g) {
    asm volatile("cp.async.cg.shared.global [%0], [%1], 16;" :: "r"(saddr), "l"(g));
}
__device__ __forceinline__ uint32_t smem_u32addr(const void* p) {
    uint32_t a;
    asm("{ .reg .u64 t; cvta.to.shared.u64 t, %1; cvt.u32.u64 %0, t; }" : "=r"(a) : "l"(p));
    return a;
}
__device__ __forceinline__ void ldmatrix_x4(uint32_t& r0, uint32_t& r1,
                                            uint32_t& r2, uint32_t& r3, uint32_t addr) {
    asm volatile("ldmatrix.sync.aligned.m8n8.x4.shared.b16 {%0,%1,%2,%3}, [%4];"
                 : "=r"(r0), "=r"(r1), "=r"(r2), "=r"(r3) : "r"(addr));
}
__device__ __forceinline__ void ldmatrix_x4_trans(uint32_t& r0, uint32_t& r1,
                                                  uint32_t& r2, uint32_t& r3, uint32_t addr) {
    asm volatile("ldmatrix.sync.aligned.m8n8.x4.trans.shared.b16 {%0,%1,%2,%3}, [%4];"
                 : "=r"(r0), "=r"(r1), "=r"(r2), "=r"(r3) : "r"(addr));
}

// ---------------------------------------------------------------------------
// Pre-convert fp32 -> fp16. 8 chunks of 1M floats: x(4) + 4 weights.
// ---------------------------------------------------------------------------
__global__ __launch_bounds__(256) void cvt_h_kernel(const float* __restrict__ x,
                                                    const float* __restrict__ w0,
                                                    const float* __restrict__ w1,
                                                    const float* __restrict__ w2,
                                                    const float* __restrict__ w3)
{
    const size_t CH = (size_t)1024 * 1024;
    int z = blockIdx.z;
    const float* src;
    __half* dst;
    if (z < 4) { src = x + z * CH; dst = g_xh + z * CH; }
    else       { src = (z==4?w0:z==5?w1:z==6?w2:w3); dst = g_wh[z-4]; }

    size_t i = ((size_t)blockIdx.x * 256 + threadIdx.x) * 4;
    float4 t = *(const float4*)(src + i);
    uint2 r;
    r.x = pack_h2(t.x, t.y);
    r.y = pack_h2(t.z, t.w);
    *(uint2*)(dst + i) = r;
}

// ---------------------------------------------------------------------------
// fp16 GEMM (NT): 128x128 CTA tile, 8 warps (256 thr), warp tile 64x32,
// ldmatrix fragment loads, BK=64 halves, 3-stage cp.async (distance 2),
// one sync per tile. Smem [row][k], stride 36 words. 2 CTAs/SM.
// (unchanged from R13 winner)
// ---------------------------------------------------------------------------
#define GK    64
#define GSTRW 36
#define GT_U32     (128 * GSTRW)
#define GSTAGE_U32 (2 * GT_U32)
#define G_SMEM_B   (3 * GSTAGE_U32 * 4)        // 110592 B

__global__ __launch_bounds__(256, 2) void gemm_h(const __half* __restrict__ A,
                                                 const __half* __restrict__ W0,
                                                 const __half* __restrict__ W1,
                                                 const __half* __restrict__ W2,
                                                 void* __restrict__ C0v,
                                                 void* __restrict__ C1v,
                                                 void* __restrict__ C2v,
                                                 int half_out)
{
    constexpr int N = D_;
    constexpr int K = D_;

    const __half* W = (blockIdx.z == 0) ? W0 : (blockIdx.z == 1) ? W1 : W2;
    void*         Cv = (blockIdx.z == 0) ? C0v : (blockIdx.z == 1) ? C1v : C2v;

    extern __shared__ uint32_t sg[];

    const int tid  = threadIdx.x;
    const int bm   = blockIdx.y * 128;
    const int bn   = blockIdx.x * 128;
    const int lane = tid & 31;
    const int warp = tid >> 5;
    const int g    = lane >> 2;
    const int tg   = lane & 3;
    const int wm   = (warp >> 2) * 64;
    const int wn   = (warp & 3) * 32;

    int crow[4], cc16[4];
#pragma unroll
    for (int it = 0; it < 4; it++) {
        int idx = it * 256 + tid;
        crow[it] = idx >> 3;
        cc16[it] = idx & 7;
    }

    const __half* Abase = A + (size_t)bm * K;
    const __half* Wbase = W + (size_t)bn * K;
    const uint32_t sb = smem_u32addr(sg);

    const uint32_t a_lane_off =
        (uint32_t)((wm + (lane & 15)) * GSTRW + 4 * (lane >> 4)) * 4;
    const uint32_t b_lane_off =
        (uint32_t)((wn + (lane & 7) + 8 * (lane >> 4)) * GSTRW + 4 * ((lane >> 3) & 1)) * 4;

    auto load_stage = [&](int s, int kf) {
        uint32_t asa = sb + (s * GSTAGE_U32) * 4;
        uint32_t bsa = asa + GT_U32 * 4;
#pragma unroll
        for (int it = 0; it < 4; it++) {
            uint32_t off = (uint32_t)(crow[it] * GSTRW + cc16[it] * 4) * 4;
            cp_async16(asa + off, Abase + (size_t)crow[it] * K + kf + cc16[it] * 8);
            cp_async16(bsa + off, Wbase + (size_t)crow[it] * K + kf + cc16[it] * 8);
        }
        asm volatile("cp.async.commit_group;");
    };

    load_stage(0, 0);
    load_stage(1, GK);

    float c[4][4][4];
#pragma unroll
    for (int mi = 0; mi < 4; mi++)
#pragma unroll
        for (int ni = 0; ni < 4; ni++)
#pragma unroll
            for (int f = 0; f < 4; f++) c[mi][ni][f] = 0.f;

    const int NT = K / GK;   // 16
    int st = 0, st2 = 2;
    for (int t = 0; t < NT; t++) {
        if (t + 1 < NT) asm volatile("cp.async.wait_group 1;");
        else            asm volatile("cp.async.wait_group 0;");
        __syncthreads();

        if (t + 2 < NT) load_stage(st2, (t + 2) * GK);

        const uint32_t As_a = sb + (st * GSTAGE_U32) * 4;
        const uint32_t Bs_a = As_a + GT_U32 * 4;

#pragma unroll
        for (int ks = 0; ks < GK / 16; ks++) {   // 4 k16 steps
            uint32_t af[4][4], bf[4][2];
#pragma unroll
            for (int mi = 0; mi < 4; mi++)
                ldmatrix_x4(af[mi][0], af[mi][1], af[mi][2], af[mi][3],
                            As_a + a_lane_off + (uint32_t)(mi * 16 * GSTRW) * 4 + ks * 32);
#pragma unroll
            for (int nb = 0; nb < 2; nb++)
                ldmatrix_x4(bf[2*nb][0], bf[2*nb][1], bf[2*nb+1][0], bf[2*nb+1][1],
                            Bs_a + b_lane_off + (uint32_t)(nb * 16 * GSTRW) * 4 + ks * 32);
#pragma unroll
            for (int mi = 0; mi < 4; mi++)
#pragma unroll
                for (int ni = 0; ni < 4; ni++)
                    mma_f16(c[mi][ni][0], c[mi][ni][1], c[mi][ni][2], c[mi][ni][3],
                            af[mi][0], af[mi][1], af[mi][2], af[mi][3],
                            bf[ni][0], bf[ni][1]);
        }

        st  = (st  == 2) ? 0 : st + 1;
        st2 = (st2 == 2) ? 0 : st2 + 1;
    }

    if (half_out) {
        __half* C = (__half*)Cv;
#pragma unroll
        for (int mi = 0; mi < 4; mi++)
#pragma unroll
            for (int ni = 0; ni < 4; ni++) {
                int row = bm + wm + mi * 16 + g;
                int col = bn + wn + ni * 8 + 2 * tg;
                *(uint32_t*)(C + (size_t)row * N + col)       = pack_h2(c[mi][ni][0], c[mi][ni][1]);
                *(uint32_t*)(C + (size_t)(row + 8) * N + col) = pack_h2(c[mi][ni][2], c[mi][ni][3]);
            }
    } else {
        float* C = (float*)Cv;
#pragma unroll
        for (int mi = 0; mi < 4; mi++)
#pragma unroll
            for (int ni = 0; ni < 4; ni++) {
                int row = bm + wm + mi * 16 + g;
                int col = bn + wn + ni * 8 + 2 * tg;
                *(float2*)(C + (size_t)row * N + col)       = make_float2(c[mi][ni][0], c[mi][ni][1]);
                *(float2*)(C + (size_t)(row + 8) * N + col) = make_float2(c[mi][ni][2], c[mi][ni][3]);
            }
    }
}

// ---------------------------------------------------------------------------
// fp16 tensor-core causal flash attention. R13 core, with the K/V pipeline
// deepened to 3 stages (prefetch distance 2, wait_group 1, one sync/tile).
// ---------------------------------------------------------------------------
#define FSTRW 36
#define FT_U32   (64 * FSTRW)
#define FA_STAGE_U32 (2 * FT_U32)              // K + V per stage
#define FA_SMEM_B (3 * FA_STAGE_U32 * 4)       // 55296 B, 2 CTAs/SM

__global__ __launch_bounds__(256, 2) void flash_attn_h(const __half* __restrict__ Qg,
                                                       const __half* __restrict__ Kg,
                                                       const __half* __restrict__ Vg,
                                                       __half* __restrict__ Og)
{
    extern __shared__ uint32_t sm[];
    const uint32_t sb = smem_u32addr(sm);

    const int qt   = (gridDim.x - 1) - blockIdx.x;   // heavy blocks first
    const int bh   = blockIdx.y;
    const int b    = bh >> 4;
    const int h    = bh & 15;
    const int tid  = threadIdx.x;
    const int lane = tid & 31;
    const int warp = tid >> 5;
    const int g    = lane >> 2;
    const int tg   = lane & 3;
    const int m0   = warp * 16;
    const int q0   = qt * 128;

    const size_t base = (size_t)b * S_ * D_ + (size_t)h * DH_;
    const int nkt = 2 * qt + 2;

    int crow[2], cc16[2];
#pragma unroll
    for (int it = 0; it < 2; it++) {
        int idx = it * 256 + tid;
        crow[it] = idx >> 3;
        cc16[it] = idx & 7;
    }

    auto load_tile = [&](int s, int k0) {
        uint32_t ksa = sb + (s * FA_STAGE_U32) * 4;
        uint32_t vsa = ksa + FT_U32 * 4;
#pragma unroll
        for (int it = 0; it < 2; it++) {
            uint32_t off = (uint32_t)(crow[it] * FSTRW + cc16[it] * 4) * 4;
            cp_async16(ksa + off, Kg + base + (size_t)(k0 + crow[it]) * D_ + cc16[it] * 8);
            cp_async16(vsa + off, Vg + base + (size_t)(k0 + crow[it]) * D_ + cc16[it] * 8);
        }
        asm volatile("cp.async.commit_group;");
    };

    // prologue: tiles 0 and 1 (nkt >= 2 always)
    load_tile(0, 0);
    load_tile(1, 64);

    const uint32_t kb_lane_off =
        (uint32_t)(((lane & 7) + 8 * (lane >> 4)) * FSTRW + 4 * ((lane >> 3) & 1)) * 4;

    uint32_t qf[4][4];
    {
        const __half* qr0 = Qg + base + (size_t)(q0 + m0 + g) * D_;
        const __half* qr1 = qr0 + 8 * D_;
#pragma unroll
        for (int ks = 0; ks < 4; ks++) {
            qf[ks][0] = *(const uint32_t*)(qr0 + ks * 16 + 2 * tg);
            qf[ks][1] = *(const uint32_t*)(qr1 + ks * 16 + 2 * tg);
            qf[ks][2] = *(const uint32_t*)(qr0 + ks * 16 + 2 * tg + 8);
            qf[ks][3] = *(const uint32_t*)(qr1 + ks * 16 + 2 * tg + 8);
        }
    }

    float o[8][4];
#pragma unroll
    for (int ni = 0; ni < 8; ni++)
#pragma unroll
        for (int f = 0; f < 4; f++) o[ni][f] = 0.f;
    float mrow[2] = {-1e30f, -1e30f};
    float lrow[2] = {0.f, 0.f};

    int st = 0, st2 = 2;
    for (int kt = 0; kt < nkt; kt++) {
        if (kt + 1 < nkt) asm volatile("cp.async.wait_group 1;");
        else              asm volatile("cp.async.wait_group 0;");
        __syncthreads();

        // issue tile kt+2 into st2 (last read at kt-1, before the sync above)
        if (kt + 2 < nkt) load_tile(st2, (kt + 2) * 64);

        const uint32_t ksa = sb + (st * FA_STAGE_U32) * 4;
        const uint32_t vsa = ksa + FT_U32 * 4;
        const int k0 = kt * 64;

        int nb_cnt = 4, ks_cnt = 4;
        const bool diag = (kt >= 2 * qt);
        if (diag) {
            int lim = m0 + 15 - (k0 - q0);
            int nic = (lim < 0) ? 0 : ((lim >> 3) + 1);
            if (nic > 8) nic = 8;
            nb_cnt = (nic + 1) >> 1;
            int ksc = (lim < 0) ? 0 : ((lim >> 4) + 1);
            if (ksc > 4) ksc = 4;
            ks_cnt = ksc;
        }

        // ---- S = Q K^T ----
        float s[8][4];
#pragma unroll
        for (int nb = 0; nb < 4; nb++) {
            if (nb < nb_cnt) {
                float* s0 = s[2*nb];
                float* s1 = s[2*nb+1];
                s0[0]=s0[1]=s0[2]=s0[3]=0.f;
                s1[0]=s1[1]=s1[2]=s1[3]=0.f;
#pragma unroll
                for (int ks = 0; ks < 4; ks++) {
                    uint32_t b0a, b1a, b0b, b1b;
                    ldmatrix_x4(b0a, b1a, b0b, b1b,
                                ksa + kb_lane_off + (uint32_t)(nb * 16 * FSTRW) * 4 + ks * 32);
                    mma_f16(s0[0], s0[1], s0[2], s0[3],
                            qf[ks][0], qf[ks][1], qf[ks][2], qf[ks][3], b0a, b1a);
                    mma_f16(s1[0], s1[1], s1[2], s1[3],
                            qf[ks][0], qf[ks][1], qf[ks][2], qf[ks][3], b0b, b1b);
                }
#pragma unroll
                for (int f = 0; f < 4; f++) { s0[f] *= 0.125f; s1[f] *= 0.125f; }
            } else {
                s[2*nb][0]=s[2*nb][1]=s[2*nb][2]=s[2*nb][3]=-1e30f;
                s[2*nb+1][0]=s[2*nb+1][1]=s[2*nb+1][2]=s[2*nb+1][3]=-1e30f;
            }
        }

        if (diag) {
            int row0 = q0 + m0 + g;
            int row1 = row0 + 8;
#pragma unroll
            for (int ni = 0; ni < 8; ni++) {
                if (ni < 2 * nb_cnt) {
                    int c0 = k0 + ni * 8 + 2 * tg;
                    if (c0     > row0) s[ni][0] = -1e30f;
                    if (c0 + 1 > row0) s[ni][1] = -1e30f;
                    if (c0     > row1) s[ni][2] = -1e30f;
                    if (c0 + 1 > row1) s[ni][3] = -1e30f;
                }
            }
        }

        // ---- online softmax ----
#pragma unroll
        for (int r2 = 0; r2 < 2; r2++) {
            float mx = -1e30f;
#pragma unroll
            for (int ni = 0; ni < 8; ni++)
                mx = fmaxf(mx, fmaxf(s[ni][2 * r2], s[ni][2 * r2 + 1]));
            mx = fmaxf(mx, __shfl_xor_sync(0xffffffffu, mx, 1));
            mx = fmaxf(mx, __shfl_xor_sync(0xffffffffu, mx, 2));
            float mnew  = fmaxf(mrow[r2], mx);
            float alpha = __expf(mrow[r2] - mnew);
            mrow[r2] = mnew;
            float rs = 0.f;
#pragma unroll
            for (int ni = 0; ni < 8; ni++) {
                float p0 = __expf(s[ni][2 * r2]     - mnew);
                float p1 = __expf(s[ni][2 * r2 + 1] - mnew);
                s[ni][2 * r2] = p0; s[ni][2 * r2 + 1] = p1;
                rs += p0 + p1;
            }
            rs += __shfl_xor_sync(0xffffffffu, rs, 1);
            rs += __shfl_xor_sync(0xffffffffu, rs, 2);
            lrow[r2] = lrow[r2] * alpha + rs;
#pragma unroll
            for (int ni = 0; ni < 8; ni++) {
                o[ni][2 * r2]     *= alpha;
                o[ni][2 * r2 + 1] *= alpha;
            }
        }

        // ---- O += P V ----
#pragma unroll
        for (int ks = 0; ks < 4; ks++) {
            if (ks < ks_cnt) {
                uint32_t a0 = pack_h2(s[2*ks][0],   s[2*ks][1]);
                uint32_t a1 = pack_h2(s[2*ks][2],   s[2*ks][3]);
                uint32_t a2 = pack_h2(s[2*ks+1][0], s[2*ks+1][1]);
                uint32_t a3 = pack_h2(s[2*ks+1][2], s[2*ks+1][3]);
                uint32_t vrow = vsa + (uint32_t)(16 * ks + (lane & 15)) * (FSTRW * 4)
                                    + (uint32_t)(lane >> 4) * 16;
#pragma unroll
                for (int nb = 0; nb < 4; nb++) {
                    uint32_t r0, r1, r2, r3;
                    ldmatrix_x4_trans(r0, r1, r2, r3, vrow + (uint32_t)nb * 32);
                    mma_f16(o[2*nb][0],   o[2*nb][1],   o[2*nb][2],   o[2*nb][3],
                            a0, a1, a2, a3, r0, r1);
                    mma_f16(o[2*nb+1][0], o[2*nb+1][1], o[2*nb+1][2], o[2*nb+1][3],
                            a0, a1, a2, a3, r2, r3);
                }
            }
        }

        st  = (st  == 2) ? 0 : st + 1;
        st2 = (st2 == 2) ? 0 : st2 + 1;
    }

    const float inv0 = 1.f / lrow[0];
    const float inv1 = 1.f / lrow[1];
    const int row0 = q0 + m0 + g;
    __half* op0 = Og + base + (size_t)row0 * D_;
    __half* op1 = op0 + 8 * D_;
#pragma unroll
    for (int ni = 0; ni < 8; ni++) {
        int col = ni * 8 + 2 * tg;
        *(uint32_t*)(op0 + col) = pack_h2(o[ni][0] * inv0, o[ni][1] * inv0);
        *(uint32_t*)(op1 + col) = pack_h2(o[ni][2] * inv1, o[ni][3] * inv1);
    }
}

// ---------------------------------------------------------------------------
extern "C" void kernel_launch(void* const* d_in, const int* in_sizes, int n_in,
                              void* d_out, int out_size)
{
    const float* x  = (const float*)d_in[0];
    const float* Wq = (const float*)d_in[1];
    const float* Wk = (const float*)d_in[2];
    const float* Wv = (const float*)d_in[3];
    const float* Wo = (const float*)d_in[4];
    float* out = (float*)d_out;

    __half *q, *k, *v, *o, *xh, *wh;
    cudaGetSymbolAddress((void**)&q,  g_q);
    cudaGetSymbolAddress((void**)&k,  g_k);
    cudaGetSymbolAddress((void**)&v,  g_v);
    cudaGetSymbolAddress((void**)&o,  g_o);
    cudaGetSymbolAddress((void**)&xh, g_xh);
    cudaGetSymbolAddress((void**)&wh, g_wh);
    const size_t WSZ = (size_t)D_ * D_;

    static bool attr_set = false;
    if (!attr_set) {
        cudaFuncSetAttribute(flash_attn_h,
                             cudaFuncAttributeMaxDynamicSharedMemorySize, FA_SMEM_B);
        cudaFuncSetAttribute(gemm_h,
                             cudaFuncAttributeMaxDynamicSharedMemorySize, G_SMEM_B);
        attr_set = true;
    }

    cvt_h_kernel<<<dim3(1024, 1, 8), 256>>>(x, Wq, Wk, Wv, Wo);

    gemm_h<<<dim3(D_ / 128, MTOT / 128, 3), 256, G_SMEM_B>>>(
        xh, wh + 0 * WSZ, wh + 1 * WSZ, wh + 2 * WSZ, q, k, v, 1);

    flash_attn_h<<<dim3(S_ / 128, B_ * H_), 256, FA_SMEM_B>>>(q, k, v, o);

    gemm_h<<<dim3(D_ / 128, MTOT / 128, 1), 256, G_SMEM_B>>>(
        o, wh + 3 * WSZ, wh + 3 * WSZ, wh + 3 * WSZ, out, out, out, 0);
}

// round 16
// speedup vs baseline: 1.0701x; 1.0701x over previous
#include <cuda_runtime.h>
#include <cuda_fp16.h>
#include <cstdint>

#define B_    2
#define S_    2048
#define D_    1024
#define H_    16
#define DH_   64
#define MTOT  (B_ * S_)

// fp16 scratch
__device__ __half g_q[(size_t)MTOT * D_];
__device__ __half g_k[(size_t)MTOT * D_];
__device__ __half g_v[(size_t)MTOT * D_];
__device__ __half g_o[(size_t)MTOT * D_];
__device__ __half g_xh[(size_t)MTOT * D_];
__device__ __half g_wh[4][(size_t)D_ * D_];

// ---------------------------------------------------------------------------
__device__ __forceinline__ uint32_t pack_h2(float lo, float hi) {
    uint32_t u;
    asm("cvt.rn.f16x2.f32 %0, %1, %2;" : "=r"(u) : "f"(hi), "f"(lo));
    return u;
}

__device__ __forceinline__ void mma_f16(float& c0, float& c1, float& c2, float& c3,
                                        uint32_t a0, uint32_t a1, uint32_t a2, uint32_t a3,
                                        uint32_t b0, uint32_t b1) {
    asm volatile(
        "mma.sync.aligned.m16n8k16.row.col.f32.f16.f16.f32 "
        "{%0,%1,%2,%3}, {%4,%5,%6,%7}, {%8,%9}, {%0,%1,%2,%3};"
        : "+f"(c0), "+f"(c1), "+f"(c2), "+f"(c3)
        : "r"(a0), "r"(a1), "r"(a2), "r"(a3), "r"(b0), "r"(b1));
}

__device__ __forceinline__ void cp_async16(uint32_t saddr, const void* g) {
    asm volatile("cp.async.cg.shared.global [%0], [%1], 16;" :: "r"(saddr), "l"(g));
}
__device__ __forceinline__ uint32_t smem_u32addr(const void* p) {
    uint32_t a;
    asm("{ .reg .u64 t; cvta.to.shared.u64 t, %1; cvt.u32.u64 %0, t; }" : "=r"(a) : "l"(p));
    return a;
}
__device__ __forceinline__ void ldmatrix_x4(uint32_t& r0, uint32_t& r1,
                                            uint32_t& r2, uint32_t& r3, uint32_t addr) {
    asm volatile("ldmatrix.sync.aligned.m8n8.x4.shared.b16 {%0,%1,%2,%3}, [%4];"
                 : "=r"(r0), "=r"(r1), "=r"(r2), "=r"(r3) : "r"(addr));
}
__device__ __forceinline__ void ldmatrix_x4_trans(uint32_t& r0, uint32_t& r1,
                                                  uint32_t& r2, uint32_t& r3, uint32_t addr) {
    asm volatile("ldmatrix.sync.aligned.m8n8.x4.trans.shared.b16 {%0,%1,%2,%3}, [%4];"
                 : "=r"(r0), "=r"(r1), "=r"(r2), "=r"(r3) : "r"(addr));
}

// ---------------------------------------------------------------------------
// Pre-convert fp32 -> fp16. 8 chunks of 1M floats: x(4) + 4 weights.
// ---------------------------------------------------------------------------
__global__ __launch_bounds__(256) void cvt_h_kernel(const float* __restrict__ x,
                                                    const float* __restrict__ w0,
                                                    const float* __restrict__ w1,
                                                    const float* __restrict__ w2,
                                                    const float* __restrict__ w3)
{
    const size_t CH = (size_t)1024 * 1024;
    int z = blockIdx.z;
    const float* src;
    __half* dst;
    if (z < 4) { src = x + z * CH; dst = g_xh + z * CH; }
    else       { src = (z==4?w0:z==5?w1:z==6?w2:w3); dst = g_wh[z-4]; }

    size_t i = ((size_t)blockIdx.x * 256 + threadIdx.x) * 4;
    float4 t = *(const float4*)(src + i);
    uint2 r;
    r.x = pack_h2(t.x, t.y);
    r.y = pack_h2(t.z, t.w);
    *(uint2*)(dst + i) = r;
}

// ---------------------------------------------------------------------------
// fp16 GEMM (NT): 128x128 CTA tile, 8 warps, warp tile 64x32, ldmatrix frags,
// BK=64 halves, 3-stage cp.async (distance 2), one sync/tile. NEW: next-stage
// cp.async issued between ks=0 and ks=1 (off the post-barrier critical path).
// ---------------------------------------------------------------------------
#define GK    64
#define GSTRW 36
#define GT_U32     (128 * GSTRW)
#define GSTAGE_U32 (2 * GT_U32)
#define G_SMEM_B   (3 * GSTAGE_U32 * 4)        // 110592 B

__global__ __launch_bounds__(256, 2) void gemm_h(const __half* __restrict__ A,
                                                 const __half* __restrict__ W0,
                                                 const __half* __restrict__ W1,
                                                 const __half* __restrict__ W2,
                                                 void* __restrict__ C0v,
                                                 void* __restrict__ C1v,
                                                 void* __restrict__ C2v,
                                                 int half_out)
{
    constexpr int N = D_;
    constexpr int K = D_;

    const __half* W = (blockIdx.z == 0) ? W0 : (blockIdx.z == 1) ? W1 : W2;
    void*         Cv = (blockIdx.z == 0) ? C0v : (blockIdx.z == 1) ? C1v : C2v;

    extern __shared__ uint32_t sg[];

    const int tid  = threadIdx.x;
    const int bm   = blockIdx.y * 128;
    const int bn   = blockIdx.x * 128;
    const int lane = tid & 31;
    const int warp = tid >> 5;
    const int g    = lane >> 2;
    const int tg   = lane & 3;
    const int wm   = (warp >> 2) * 64;
    const int wn   = (warp & 3) * 32;

    int crow[4], cc16[4];
#pragma unroll
    for (int it = 0; it < 4; it++) {
        int idx = it * 256 + tid;
        crow[it] = idx >> 3;
        cc16[it] = idx & 7;
    }

    const __half* Abase = A + (size_t)bm * K;
    const __half* Wbase = W + (size_t)bn * K;
    const uint32_t sb = smem_u32addr(sg);

    const uint32_t a_lane_off =
        (uint32_t)((wm + (lane & 15)) * GSTRW + 4 * (lane >> 4)) * 4;
    const uint32_t b_lane_off =
        (uint32_t)((wn + (lane & 7) + 8 * (lane >> 4)) * GSTRW + 4 * ((lane >> 3) & 1)) * 4;

    auto load_stage = [&](int s, int kf) {
        uint32_t asa = sb + (s * GSTAGE_U32) * 4;
        uint32_t bsa = asa + GT_U32 * 4;
#pragma unroll
        for (int it = 0; it < 4; it++) {
            uint32_t off = (uint32_t)(crow[it] * GSTRW + cc16[it] * 4) * 4;
            cp_async16(asa + off, Abase + (size_t)crow[it] * K + kf + cc16[it] * 8);
            cp_async16(bsa + off, Wbase + (size_t)crow[it] * K + kf + cc16[it] * 8);
        }
        asm volatile("cp.async.commit_group;");
    };

    load_stage(0, 0);
    load_stage(1, GK);

    float c[4][4][4];
#pragma unroll
    for (int mi = 0; mi < 4; mi++)
#pragma unroll
        for (int ni = 0; ni < 4; ni++)
#pragma unroll
            for (int f = 0; f < 4; f++) c[mi][ni][f] = 0.f;

    const int NT = K / GK;   // 16
    int st = 0, st2 = 2;
    for (int t = 0; t < NT; t++) {
        if (t + 1 < NT) asm volatile("cp.async.wait_group 1;");
        else            asm volatile("cp.async.wait_group 0;");
        __syncthreads();

        const uint32_t As_a = sb + (st * GSTAGE_U32) * 4;
        const uint32_t Bs_a = As_a + GT_U32 * 4;

#pragma unroll
        for (int ks = 0; ks < GK / 16; ks++) {   // 4 k16 steps
            uint32_t af[4][4], bf[4][2];
#pragma unroll
            for (int mi = 0; mi < 4; mi++)
                ldmatrix_x4(af[mi][0], af[mi][1], af[mi][2], af[mi][3],
                            As_a + a_lane_off + (uint32_t)(mi * 16 * GSTRW) * 4 + ks * 32);
#pragma unroll
            for (int nb = 0; nb < 2; nb++)
                ldmatrix_x4(bf[2*nb][0], bf[2*nb][1], bf[2*nb+1][0], bf[2*nb+1][1],
                            Bs_a + b_lane_off + (uint32_t)(nb * 16 * GSTRW) * 4 + ks * 32);
#pragma unroll
            for (int mi = 0; mi < 4; mi++)
#pragma unroll
                for (int ni = 0; ni < 4; ni++)
                    mma_f16(c[mi][ni][0], c[mi][ni][1], c[mi][ni][2], c[mi][ni][3],
                            af[mi][0], af[mi][1], af[mi][2], af[mi][3],
                            bf[ni][0], bf[ni][1]);

            // issue next prefetch AFTER the first compute group is in flight
            if (ks == 0 && t + 2 < NT) load_stage(st2, (t + 2) * GK);
        }

        st  = (st  == 2) ? 0 : st + 1;
        st2 = (st2 == 2) ? 0 : st2 + 1;
    }

    if (half_out) {
        __half* C = (__half*)Cv;
#pragma unroll
        for (int mi = 0; mi < 4; mi++)
#pragma unroll
            for (int ni = 0; ni < 4; ni++) {
                int row = bm + wm + mi * 16 + g;
                int col = bn + wn + ni * 8 + 2 * tg;
                *(uint32_t*)(C + (size_t)row * N + col)       = pack_h2(c[mi][ni][0], c[mi][ni][1]);
                *(uint32_t*)(C + (size_t)(row + 8) * N + col) = pack_h2(c[mi][ni][2], c[mi][ni][3]);
            }
    } else {
        float* C = (float*)Cv;
#pragma unroll
        for (int mi = 0; mi < 4; mi++)
#pragma unroll
            for (int ni = 0; ni < 4; ni++) {
                int row = bm + wm + mi * 16 + g;
                int col = bn + wn + ni * 8 + 2 * tg;
                *(float2*)(C + (size_t)row * N + col)       = make_float2(c[mi][ni][0], c[mi][ni][1]);
                *(float2*)(C + (size_t)(row + 8) * N + col) = make_float2(c[mi][ni][2], c[mi][ni][3]);
            }
    }
}

// ---------------------------------------------------------------------------
// fp16 tensor-core causal flash attention. R13 2-stage core; NEW: next-tile
// cp.async issued after the S=QK^T mma block (off the post-barrier path).
// ---------------------------------------------------------------------------
#define FSTRW 36
#define FT_U32   (64 * FSTRW)
#define FA_SMEM_B (4 * FT_U32 * 4)             // 36864 B

__global__ __launch_bounds__(256, 2) void flash_attn_h(const __half* __restrict__ Qg,
                                                       const __half* __restrict__ Kg,
                                                       const __half* __restrict__ Vg,
                                                       __half* __restrict__ Og)
{
    extern __shared__ uint32_t sm[];
    const uint32_t sb = smem_u32addr(sm);

    const int qt   = (gridDim.x - 1) - blockIdx.x;   // heavy blocks first
    const int bh   = blockIdx.y;
    const int b    = bh >> 4;
    const int h    = bh & 15;
    const int tid  = threadIdx.x;
    const int lane = tid & 31;
    const int warp = tid >> 5;
    const int g    = lane >> 2;
    const int tg   = lane & 3;
    const int m0   = warp * 16;
    const int q0   = qt * 128;

    const size_t base = (size_t)b * S_ * D_ + (size_t)h * DH_;
    const int nkt = 2 * qt + 2;

    int crow[2], cc16[2];
#pragma unroll
    for (int it = 0; it < 2; it++) {
        int idx = it * 256 + tid;
        crow[it] = idx >> 3;
        cc16[it] = idx & 7;
    }

    auto load_tile = [&](int s, int k0) {
        uint32_t ksa = sb + (s * 2 * FT_U32) * 4;
        uint32_t vsa = ksa + FT_U32 * 4;
#pragma unroll
        for (int it = 0; it < 2; it++) {
            uint32_t off = (uint32_t)(crow[it] * FSTRW + cc16[it] * 4) * 4;
            cp_async16(ksa + off, Kg + base + (size_t)(k0 + crow[it]) * D_ + cc16[it] * 8);
            cp_async16(vsa + off, Vg + base + (size_t)(k0 + crow[it]) * D_ + cc16[it] * 8);
        }
        asm volatile("cp.async.commit_group;");
    };

    load_tile(0, 0);

    const uint32_t kb_lane_off =
        (uint32_t)(((lane & 7) + 8 * (lane >> 4)) * FSTRW + 4 * ((lane >> 3) & 1)) * 4;

    uint32_t qf[4][4];
    {
        const __half* qr0 = Qg + base + (size_t)(q0 + m0 + g) * D_;
        const __half* qr1 = qr0 + 8 * D_;
#pragma unroll
        for (int ks = 0; ks < 4; ks++) {
            qf[ks][0] = *(const uint32_t*)(qr0 + ks * 16 + 2 * tg);
            qf[ks][1] = *(const uint32_t*)(qr1 + ks * 16 + 2 * tg);
            qf[ks][2] = *(const uint32_t*)(qr0 + ks * 16 + 2 * tg + 8);
            qf[ks][3] = *(const uint32_t*)(qr1 + ks * 16 + 2 * tg + 8);
        }
    }

    float o[8][4];
#pragma unroll
    for (int ni = 0; ni < 8; ni++)
#pragma unroll
        for (int f = 0; f < 4; f++) o[ni][f] = 0.f;
    float mrow[2] = {-1e30f, -1e30f};
    float lrow[2] = {0.f, 0.f};

    for (int kt = 0; kt < nkt; kt++) {
        const int buf = kt & 1;

        asm volatile("cp.async.wait_group 0;");
        __syncthreads();

        const uint32_t ksa = sb + (buf * 2 * FT_U32) * 4;
        const uint32_t vsa = ksa + FT_U32 * 4;
        const int k0 = kt * 64;

        int nb_cnt = 4, ks_cnt = 4;
        const bool diag = (kt >= 2 * qt);
        if (diag) {
            int lim = m0 + 15 - (k0 - q0);
            int nic = (lim < 0) ? 0 : ((lim >> 3) + 1);
            if (nic > 8) nic = 8;
            nb_cnt = (nic + 1) >> 1;
            int ksc = (lim < 0) ? 0 : ((lim >> 4) + 1);
            if (ksc > 4) ksc = 4;
            ks_cnt = ksc;
        }

        // ---- S = Q K^T ----
        float s[8][4];
#pragma unroll
        for (int nb = 0; nb < 4; nb++) {
            if (nb < nb_cnt) {
                float* s0 = s[2*nb];
                float* s1 = s[2*nb+1];
                s0[0]=s0[1]=s0[2]=s0[3]=0.f;
                s1[0]=s1[1]=s1[2]=s1[3]=0.f;
#pragma unroll
                for (int ks = 0; ks < 4; ks++) {
                    uint32_t b0a, b1a, b0b, b1b;
                    ldmatrix_x4(b0a, b1a, b0b, b1b,
                                ksa + kb_lane_off + (uint32_t)(nb * 16 * FSTRW) * 4 + ks * 32);
                    mma_f16(s0[0], s0[1], s0[2], s0[3],
                            qf[ks][0], qf[ks][1], qf[ks][2], qf[ks][3], b0a, b1a);
                    mma_f16(s1[0], s1[1], s1[2], s1[3],
                            qf[ks][0], qf[ks][1], qf[ks][2], qf[ks][3], b0b, b1b);
                }
#pragma unroll
                for (int f = 0; f < 4; f++) { s0[f] *= 0.125f; s1[f] *= 0.125f; }
            } else {
                s[2*nb][0]=s[2*nb][1]=s[2*nb][2]=s[2*nb][3]=-1e30f;
                s[2*nb+1][0]=s[2*nb+1][1]=s[2*nb+1][2]=s[2*nb+1][3]=-1e30f;
            }
        }

        // issue next tile's loads now (plenty of slack: softmax+PV remain)
        if (kt + 1 < nkt) load_tile(buf ^ 1, (kt + 1) * 64);

        if (diag) {
            int row0 = q0 + m0 + g;
            int row1 = row0 + 8;
#pragma unroll
            for (int ni = 0; ni < 8; ni++) {
                if (ni < 2 * nb_cnt) {
                    int c0 = k0 + ni * 8 + 2 * tg;
                    if (c0     > row0) s[ni][0] = -1e30f;
                    if (c0 + 1 > row0) s[ni][1] = -1e30f;
                    if (c0     > row1) s[ni][2] = -1e30f;
                    if (c0 + 1 > row1) s[ni][3] = -1e30f;
                }
            }
        }

        // ---- online softmax ----
#pragma unroll
        for (int r2 = 0; r2 < 2; r2++) {
            float mx = -1e30f;
#pragma unroll
            for (int ni = 0; ni < 8; ni++)
                mx = fmaxf(mx, fmaxf(s[ni][2 * r2], s[ni][2 * r2 + 1]));
            mx = fmaxf(mx, __shfl_xor_sync(0xffffffffu, mx, 1));
            mx = fmaxf(mx, __shfl_xor_sync(0xffffffffu, mx, 2));
            float mnew  = fmaxf(mrow[r2], mx);
            float alpha = __expf(mrow[r2] - mnew);
            mrow[r2] = mnew;
            float rs = 0.f;
#pragma unroll
            for (int ni = 0; ni < 8; ni++) {
                float p0 = __expf(s[ni][2 * r2]     - mnew);
                float p1 = __expf(s[ni][2 * r2 + 1] - mnew);
                s[ni][2 * r2] = p0; s[ni][2 * r2 + 1] = p1;
                rs += p0 + p1;
            }
            rs += __shfl_xor_sync(0xffffffffu, rs, 1);
            rs += __shfl_xor_sync(0xffffffffu, rs, 2);
            lrow[r2] = lrow[r2] * alpha + rs;
#pragma unroll
            for (int ni = 0; ni < 8; ni++) {
                o[ni][2 * r2]     *= alpha;
                o[ni][2 * r2 + 1] *= alpha;
            }
        }

        // ---- O += P V ----
#pragma unroll
        for (int ks = 0; ks < 4; ks++) {
            if (ks < ks_cnt) {
                uint32_t a0 = pack_h2(s[2*ks][0],   s[2*ks][1]);
                uint32_t a1 = pack_h2(s[2*ks][2],   s[2*ks][3]);
                uint32_t a2 = pack_h2(s[2*ks+1][0], s[2*ks+1][1]);
                uint32_t a3 = pack_h2(s[2*ks+1][2], s[2*ks+1][3]);
                uint32_t vrow = vsa + (uint32_t)(16 * ks + (lane & 15)) * (FSTRW * 4)
                                    + (uint32_t)(lane >> 4) * 16;
#pragma unroll
                for (int nb = 0; nb < 4; nb++) {
                    uint32_t r0, r1, r2, r3;
                    ldmatrix_x4_trans(r0, r1, r2, r3, vrow + (uint32_t)nb * 32);
                    mma_f16(o[2*nb][0],   o[2*nb][1],   o[2*nb][2],   o[2*nb][3],
                            a0, a1, a2, a3, r0, r1);
                    mma_f16(o[2*nb+1][0], o[2*nb+1][1], o[2*nb+1][2], o[2*nb+1][3],
                            a0, a1, a2, a3, r2, r3);
                }
            }
        }
    }

    const float inv0 = 1.f / lrow[0];
    const float inv1 = 1.f / lrow[1];
    const int row0 = q0 + m0 + g;
    __half* op0 = Og + base + (size_t)row0 * D_;
    __half* op1 = op0 + 8 * D_;
#pragma unroll
    for (int ni = 0; ni < 8; ni++) {
        int col = ni * 8 + 2 * tg;
        *(uint32_t*)(op0 + col) = pack_h2(o[ni][0] * inv0, o[ni][1] * inv0);
        *(uint32_t*)(op1 + col) = pack_h2(o[ni][2] * inv1, o[ni][3] * inv1);
    }
}

// ---------------------------------------------------------------------------
extern "C" void kernel_launch(void* const* d_in, const int* in_sizes, int n_in,
                              void* d_out, int out_size)
{
    const float* x  = (const float*)d_in[0];
    const float* Wq = (const float*)d_in[1];
    const float* Wk = (const float*)d_in[2];
    const float* Wv = (const float*)d_in[3];
    const float* Wo = (const float*)d_in[4];
    float* out = (float*)d_out;

    __half *q, *k, *v, *o, *xh, *wh;
    cudaGetSymbolAddress((void**)&q,  g_q);
    cudaGetSymbolAddress((void**)&k,  g_k);
    cudaGetSymbolAddress((void**)&v,  g_v);
    cudaGetSymbolAddress((void**)&o,  g_o);
    cudaGetSymbolAddress((void**)&xh, g_xh);
    cudaGetSymbolAddress((void**)&wh, g_wh);
    const size_t WSZ = (size_t)D_ * D_;

    static bool attr_set = false;
    if (!attr_set) {
        cudaFuncSetAttribute(flash_attn_h,
                             cudaFuncAttributeMaxDynamicSharedMemorySize, FA_SMEM_B);
        cudaFuncSetAttribute(gemm_h,
                             cudaFuncAttributeMaxDynamicSharedMemorySize, G_SMEM_B);
        attr_set = true;
    }

    cvt_h_kernel<<<dim3(1024, 1, 8), 256>>>(x, Wq, Wk, Wv, Wo);

    gemm_h<<<dim3(D_ / 128, MTOT / 128, 3), 256, G_SMEM_B>>>(
        xh, wh + 0 * WSZ, wh + 1 * WSZ, wh + 2 * WSZ, q, k, v, 1);

    flash_attn_h<<<dim3(S_ / 128, B_ * H_), 256, FA_SMEM_B>>>(q, k, v, o);

    gemm_h<<<dim3(D_ / 128, MTOT / 128, 1), 256, G_SMEM_B>>>(
        o, wh + 3 * WSZ, wh + 3 * WSZ, wh + 3 * WSZ, out, out, out, 0);
}

// round 17
// speedup vs baseline: 1.0784x; 1.0077x over previous
#include <cuda_runtime.h>
#include <cuda_fp16.h>
#include <cstdint>

#define B_    2
#define S_    2048
#define D_    1024
#define H_    16
#define DH_   64
#define MTOT  (B_ * S_)

// fp16 scratch
__device__ __half g_q[(size_t)MTOT * D_];
__device__ __half g_k[(size_t)MTOT * D_];
__device__ __half g_v[(size_t)MTOT * D_];
__device__ __half g_o[(size_t)MTOT * D_];
__device__ __half g_xh[(size_t)MTOT * D_];
__device__ __half g_wh[4][(size_t)D_ * D_];

// ---------------------------------------------------------------------------
__device__ __forceinline__ uint32_t pack_h2(float lo, float hi) {
    uint32_t u;
    asm("cvt.rn.f16x2.f32 %0, %1, %2;" : "=r"(u) : "f"(hi), "f"(lo));
    return u;
}

__device__ __forceinline__ void mma_f16(float& c0, float& c1, float& c2, float& c3,
                                        uint32_t a0, uint32_t a1, uint32_t a2, uint32_t a3,
                                        uint32_t b0, uint32_t b1) {
    asm volatile(
        "mma.sync.aligned.m16n8k16.row.col.f32.f16.f16.f32 "
        "{%0,%1,%2,%3}, {%4,%5,%6,%7}, {%8,%9}, {%0,%1,%2,%3};"
        : "+f"(c0), "+f"(c1), "+f"(c2), "+f"(c3)
        : "r"(a0), "r"(a1), "r"(a2), "r"(a3), "r"(b0), "r"(b1));
}

__device__ __forceinline__ void cp_async16(uint32_t saddr, const void* g) {
    asm volatile("cp.async.cg.shared.global [%0], [%1], 16;" :: "r"(saddr), "l"(g));
}
__device__ __forceinline__ uint32_t smem_u32addr(const void* p) {
    uint32_t a;
    asm("{ .reg .u64 t; cvta.to.shared.u64 t, %1; cvt.u32.u64 %0, t; }" : "=r"(a) : "l"(p));
    return a;
}
__device__ __forceinline__ void ldmatrix_x4(uint32_t& r0, uint32_t& r1,
                                            uint32_t& r2, uint32_t& r3, uint32_t addr) {
    asm volatile("ldmatrix.sync.aligned.m8n8.x4.shared.b16 {%0,%1,%2,%3}, [%4];"
                 : "=r"(r0), "=r"(r1), "=r"(r2), "=r"(r3) : "r"(addr));
}
__device__ __forceinline__ void ldmatrix_x4_trans(uint32_t& r0, uint32_t& r1,
                                                  uint32_t& r2, uint32_t& r3, uint32_t addr) {
    asm volatile("ldmatrix.sync.aligned.m8n8.x4.trans.shared.b16 {%0,%1,%2,%3}, [%4];"
                 : "=r"(r0), "=r"(r1), "=r"(r2), "=r"(r3) : "r"(addr));
}

// ---------------------------------------------------------------------------
// Pre-convert fp32 -> fp16. 8 chunks of 1M floats: x(4) + 4 weights.
// ---------------------------------------------------------------------------
__global__ __launch_bounds__(256) void cvt_h_kernel(const float* __restrict__ x,
                                                    const float* __restrict__ w0,
                                                    const float* __restrict__ w1,
                                                    const float* __restrict__ w2,
                                                    const float* __restrict__ w3)
{
    const size_t CH = (size_t)1024 * 1024;
    int z = blockIdx.z;
    const float* src;
    __half* dst;
    if (z < 4) { src = x + z * CH; dst = g_xh + z * CH; }
    else       { src = (z==4?w0:z==5?w1:z==6?w2:w3); dst = g_wh[z-4]; }

    size_t i = ((size_t)blockIdx.x * 256 + threadIdx.x) * 4;
    float4 t = *(const float4*)(src + i);
    uint2 r;
    r.x = pack_h2(t.x, t.y);
    r.y = pack_h2(t.z, t.w);
    *(uint2*)(dst + i) = r;
}

// ---------------------------------------------------------------------------
// fp16 GEMM (NT): 128x128 CTA tile, 8 warps, warp tile 64x32, ldmatrix frags,
// BK=64 halves, 3-stage cp.async (distance 2), one sync/tile, prefetch issued
// between ks=0 and ks=1. NEW: Q output (z==0, half_out) pre-scaled by 1/8
// (exact power-of-2; bit-identical to scaling in flash).
// ---------------------------------------------------------------------------
#define GK    64
#define GSTRW 36
#define GT_U32     (128 * GSTRW)
#define GSTAGE_U32 (2 * GT_U32)
#define G_SMEM_B   (3 * GSTAGE_U32 * 4)        // 110592 B

__global__ __launch_bounds__(256, 2) void gemm_h(const __half* __restrict__ A,
                                                 const __half* __restrict__ W0,
                                                 const __half* __restrict__ W1,
                                                 const __half* __restrict__ W2,
                                                 void* __restrict__ C0v,
                                                 void* __restrict__ C1v,
                                                 void* __restrict__ C2v,
                                                 int half_out)
{
    constexpr int N = D_;
    constexpr int K = D_;

    const __half* W = (blockIdx.z == 0) ? W0 : (blockIdx.z == 1) ? W1 : W2;
    void*         Cv = (blockIdx.z == 0) ? C0v : (blockIdx.z == 1) ? C1v : C2v;
    const float oscale = (half_out && blockIdx.z == 0) ? 0.125f : 1.0f;

    extern __shared__ uint32_t sg[];

    const int tid  = threadIdx.x;
    const int bm   = blockIdx.y * 128;
    const int bn   = blockIdx.x * 128;
    const int lane = tid & 31;
    const int warp = tid >> 5;
    const int g    = lane >> 2;
    const int tg   = lane & 3;
    const int wm   = (warp >> 2) * 64;
    const int wn   = (warp & 3) * 32;

    int crow[4], cc16[4];
#pragma unroll
    for (int it = 0; it < 4; it++) {
        int idx = it * 256 + tid;
        crow[it] = idx >> 3;
        cc16[it] = idx & 7;
    }

    const __half* Abase = A + (size_t)bm * K;
    const __half* Wbase = W + (size_t)bn * K;
    const uint32_t sb = smem_u32addr(sg);

    const uint32_t a_lane_off =
        (uint32_t)((wm + (lane & 15)) * GSTRW + 4 * (lane >> 4)) * 4;
    const uint32_t b_lane_off =
        (uint32_t)((wn + (lane & 7) + 8 * (lane >> 4)) * GSTRW + 4 * ((lane >> 3) & 1)) * 4;

    auto load_stage = [&](int s, int kf) {
        uint32_t asa = sb + (s * GSTAGE_U32) * 4;
        uint32_t bsa = asa + GT_U32 * 4;
#pragma unroll
        for (int it = 0; it < 4; it++) {
            uint32_t off = (uint32_t)(crow[it] * GSTRW + cc16[it] * 4) * 4;
            cp_async16(asa + off, Abase + (size_t)crow[it] * K + kf + cc16[it] * 8);
            cp_async16(bsa + off, Wbase + (size_t)crow[it] * K + kf + cc16[it] * 8);
        }
        asm volatile("cp.async.commit_group;");
    };

    load_stage(0, 0);
    load_stage(1, GK);

    float c[4][4][4];
#pragma unroll
    for (int mi = 0; mi < 4; mi++)
#pragma unroll
        for (int ni = 0; ni < 4; ni++)
#pragma unroll
            for (int f = 0; f < 4; f++) c[mi][ni][f] = 0.f;

    const int NT = K / GK;   // 16
    int st = 0, st2 = 2;
    for (int t = 0; t < NT; t++) {
        if (t + 1 < NT) asm volatile("cp.async.wait_group 1;");
        else            asm volatile("cp.async.wait_group 0;");
        __syncthreads();

        const uint32_t As_a = sb + (st * GSTAGE_U32) * 4;
        const uint32_t Bs_a = As_a + GT_U32 * 4;

#pragma unroll
        for (int ks = 0; ks < GK / 16; ks++) {   // 4 k16 steps
            uint32_t af[4][4], bf[4][2];
#pragma unroll
            for (int mi = 0; mi < 4; mi++)
                ldmatrix_x4(af[mi][0], af[mi][1], af[mi][2], af[mi][3],
                            As_a + a_lane_off + (uint32_t)(mi * 16 * GSTRW) * 4 + ks * 32);
#pragma unroll
            for (int nb = 0; nb < 2; nb++)
                ldmatrix_x4(bf[2*nb][0], bf[2*nb][1], bf[2*nb+1][0], bf[2*nb+1][1],
                            Bs_a + b_lane_off + (uint32_t)(nb * 16 * GSTRW) * 4 + ks * 32);
#pragma unroll
            for (int mi = 0; mi < 4; mi++)
#pragma unroll
                for (int ni = 0; ni < 4; ni++)
                    mma_f16(c[mi][ni][0], c[mi][ni][1], c[mi][ni][2], c[mi][ni][3],
                            af[mi][0], af[mi][1], af[mi][2], af[mi][3],
                            bf[ni][0], bf[ni][1]);

            if (ks == 0 && t + 2 < NT) load_stage(st2, (t + 2) * GK);
        }

        st  = (st  == 2) ? 0 : st + 1;
        st2 = (st2 == 2) ? 0 : st2 + 1;
    }

    if (half_out) {
        __half* C = (__half*)Cv;
#pragma unroll
        for (int mi = 0; mi < 4; mi++)
#pragma unroll
            for (int ni = 0; ni < 4; ni++) {
                int row = bm + wm + mi * 16 + g;
                int col = bn + wn + ni * 8 + 2 * tg;
                *(uint32_t*)(C + (size_t)row * N + col) =
                    pack_h2(c[mi][ni][0] * oscale, c[mi][ni][1] * oscale);
                *(uint32_t*)(C + (size_t)(row + 8) * N + col) =
                    pack_h2(c[mi][ni][2] * oscale, c[mi][ni][3] * oscale);
            }
    } else {
        float* C = (float*)Cv;
#pragma unroll
        for (int mi = 0; mi < 4; mi++)
#pragma unroll
            for (int ni = 0; ni < 4; ni++) {
                int row = bm + wm + mi * 16 + g;
                int col = bn + wn + ni * 8 + 2 * tg;
                *(float2*)(C + (size_t)row * N + col)       = make_float2(c[mi][ni][0], c[mi][ni][1]);
                *(float2*)(C + (size_t)(row + 8) * N + col) = make_float2(c[mi][ni][2], c[mi][ni][3]);
            }
    }
}

// ---------------------------------------------------------------------------
// fp16 tensor-core causal flash attention. R15 core; NEW: Q pre-scaled (no
// per-tile S scaling) and warp-uniform alpha==1 rescale skip (bit-identical).
// ---------------------------------------------------------------------------
#define FSTRW 36
#define FT_U32   (64 * FSTRW)
#define FA_SMEM_B (4 * FT_U32 * 4)             // 36864 B

__global__ __launch_bounds__(256, 2) void flash_attn_h(const __half* __restrict__ Qg,
                                                       const __half* __restrict__ Kg,
                                                       const __half* __restrict__ Vg,
                                                       __half* __restrict__ Og)
{
    extern __shared__ uint32_t sm[];
    const uint32_t sb = smem_u32addr(sm);

    const int qt   = (gridDim.x - 1) - blockIdx.x;   // heavy blocks first
    const int bh   = blockIdx.y;
    const int b    = bh >> 4;
    const int h    = bh & 15;
    const int tid  = threadIdx.x;
    const int lane = tid & 31;
    const int warp = tid >> 5;
    const int g    = lane >> 2;
    const int tg   = lane & 3;
    const int m0   = warp * 16;
    const int q0   = qt * 128;

    const size_t base = (size_t)b * S_ * D_ + (size_t)h * DH_;
    const int nkt = 2 * qt + 2;

    int crow[2], cc16[2];
#pragma unroll
    for (int it = 0; it < 2; it++) {
        int idx = it * 256 + tid;
        crow[it] = idx >> 3;
        cc16[it] = idx & 7;
    }

    auto load_tile = [&](int s, int k0) {
        uint32_t ksa = sb + (s * 2 * FT_U32) * 4;
        uint32_t vsa = ksa + FT_U32 * 4;
#pragma unroll
        for (int it = 0; it < 2; it++) {
            uint32_t off = (uint32_t)(crow[it] * FSTRW + cc16[it] * 4) * 4;
            cp_async16(ksa + off, Kg + base + (size_t)(k0 + crow[it]) * D_ + cc16[it] * 8);
            cp_async16(vsa + off, Vg + base + (size_t)(k0 + crow[it]) * D_ + cc16[it] * 8);
        }
        asm volatile("cp.async.commit_group;");
    };

    load_tile(0, 0);

    const uint32_t kb_lane_off =
        (uint32_t)(((lane & 7) + 8 * (lane >> 4)) * FSTRW + 4 * ((lane >> 3) & 1)) * 4;

    uint32_t qf[4][4];
    {
        const __half* qr0 = Qg + base + (size_t)(q0 + m0 + g) * D_;
        const __half* qr1 = qr0 + 8 * D_;
#pragma unroll
        for (int ks = 0; ks < 4; ks++) {
            qf[ks][0] = *(const uint32_t*)(qr0 + ks * 16 + 2 * tg);
            qf[ks][1] = *(const uint32_t*)(qr1 + ks * 16 + 2 * tg);
            qf[ks][2] = *(const uint32_t*)(qr0 + ks * 16 + 2 * tg + 8);
            qf[ks][3] = *(const uint32_t*)(qr1 + ks * 16 + 2 * tg + 8);
        }
    }

    float o[8][4];
#pragma unroll
    for (int ni = 0; ni < 8; ni++)
#pragma unroll
        for (int f = 0; f < 4; f++) o[ni][f] = 0.f;
    float mrow[2] = {-1e30f, -1e30f};
    float lrow[2] = {0.f, 0.f};

    for (int kt = 0; kt < nkt; kt++) {
        const int buf = kt & 1;

        asm volatile("cp.async.wait_group 0;");
        __syncthreads();

        const uint32_t ksa = sb + (buf * 2 * FT_U32) * 4;
        const uint32_t vsa = ksa + FT_U32 * 4;
        const int k0 = kt * 64;

        int nb_cnt = 4, ks_cnt = 4;
        const bool diag = (kt >= 2 * qt);
        if (diag) {
            int lim = m0 + 15 - (k0 - q0);
            int nic = (lim < 0) ? 0 : ((lim >> 3) + 1);
            if (nic > 8) nic = 8;
            nb_cnt = (nic + 1) >> 1;
            int ksc = (lim < 0) ? 0 : ((lim >> 4) + 1);
            if (ksc > 4) ksc = 4;
            ks_cnt = ksc;
        }

        // ---- S = (Q/8) K^T (Q pre-scaled by the QKV GEMM) ----
        float s[8][4];
#pragma unroll
        for (int nb = 0; nb < 4; nb++) {
            if (nb < nb_cnt) {
                float* s0 = s[2*nb];
                float* s1 = s[2*nb+1];
                s0[0]=s0[1]=s0[2]=s0[3]=0.f;
                s1[0]=s1[1]=s1[2]=s1[3]=0.f;
#pragma unroll
                for (int ks = 0; ks < 4; ks++) {
                    uint32_t b0a, b1a, b0b, b1b;
                    ldmatrix_x4(b0a, b1a, b0b, b1b,
                                ksa + kb_lane_off + (uint32_t)(nb * 16 * FSTRW) * 4 + ks * 32);
                    mma_f16(s0[0], s0[1], s0[2], s0[3],
                            qf[ks][0], qf[ks][1], qf[ks][2], qf[ks][3], b0a, b1a);
                    mma_f16(s1[0], s1[1], s1[2], s1[3],
                            qf[ks][0], qf[ks][1], qf[ks][2], qf[ks][3], b0b, b1b);
                }
            } else {
                s[2*nb][0]=s[2*nb][1]=s[2*nb][2]=s[2*nb][3]=-1e30f;
                s[2*nb+1][0]=s[2*nb+1][1]=s[2*nb+1][2]=s[2*nb+1][3]=-1e30f;
            }
        }

        // issue next tile's loads now (softmax+PV provide the slack)
        if (kt + 1 < nkt) load_tile(buf ^ 1, (kt + 1) * 64);

        if (diag) {
            int row0 = q0 + m0 + g;
            int row1 = row0 + 8;
#pragma unroll
            for (int ni = 0; ni < 8; ni++) {
                if (ni < 2 * nb_cnt) {
                    int c0 = k0 + ni * 8 + 2 * tg;
                    if (c0     > row0) s[ni][0] = -1e30f;
                    if (c0 + 1 > row0) s[ni][1] = -1e30f;
                    if (c0     > row1) s[ni][2] = -1e30f;
                    if (c0 + 1 > row1) s[ni][3] = -1e30f;
                }
            }
        }

        // ---- online softmax ----
        float alpha2[2];
#pragma unroll
        for (int r2 = 0; r2 < 2; r2++) {
            float mx = -1e30f;
#pragma unroll
            for (int ni = 0; ni < 8; ni++)
                mx = fmaxf(mx, fmaxf(s[ni][2 * r2], s[ni][2 * r2 + 1]));
            mx = fmaxf(mx, __shfl_xor_sync(0xffffffffu, mx, 1));
            mx = fmaxf(mx, __shfl_xor_sync(0xffffffffu, mx, 2));
            float mnew  = fmaxf(mrow[r2], mx);
            float alpha = __expf(mrow[r2] - mnew);
            mrow[r2] = mnew;
            alpha2[r2] = alpha;
            float rs = 0.f;
#pragma unroll
            for (int ni = 0; ni < 8; ni++) {
                float p0 = __expf(s[ni][2 * r2]     - mnew);
                float p1 = __expf(s[ni][2 * r2 + 1] - mnew);
                s[ni][2 * r2] = p0; s[ni][2 * r2 + 1] = p1;
                rs += p0 + p1;
            }
            rs += __shfl_xor_sync(0xffffffffu, rs, 1);
            rs += __shfl_xor_sync(0xffffffffu, rs, 2);
            lrow[r2] = lrow[r2] * alpha2[r2] + rs;
        }

        // rescale O only if some lane saw a new max (alpha==1 -> identity)
        if (!__all_sync(0xffffffffu,
                        (alpha2[0] == 1.0f) && (alpha2[1] == 1.0f))) {
#pragma unroll
            for (int ni = 0; ni < 8; ni++) {
                o[ni][0] *= alpha2[0];
                o[ni][1] *= alpha2[0];
                o[ni][2] *= alpha2[1];
                o[ni][3] *= alpha2[1];
            }
        }

        // ---- O += P V ----
#pragma unroll
        for (int ks = 0; ks < 4; ks++) {
            if (ks < ks_cnt) {
                uint32_t a0 = pack_h2(s[2*ks][0],   s[2*ks][1]);
                uint32_t a1 = pack_h2(s[2*ks][2],   s[2*ks][3]);
                uint32_t a2 = pack_h2(s[2*ks+1][0], s[2*ks+1][1]);
                uint32_t a3 = pack_h2(s[2*ks+1][2], s[2*ks+1][3]);
                uint32_t vrow = vsa + (uint32_t)(16 * ks + (lane & 15)) * (FSTRW * 4)
                                    + (uint32_t)(lane >> 4) * 16;
#pragma unroll
                for (int nb = 0; nb < 4; nb++) {
                    uint32_t r0, r1, r2, r3;
                    ldmatrix_x4_trans(r0, r1, r2, r3, vrow + (uint32_t)nb * 32);
                    mma_f16(o[2*nb][0],   o[2*nb][1],   o[2*nb][2],   o[2*nb][3],
                            a0, a1, a2, a3, r0, r1);
                    mma_f16(o[2*nb+1][0], o[2*nb+1][1], o[2*nb+1][2], o[2*nb+1][3],
                            a0, a1, a2, a3, r2, r3);
                }
            }
        }
    }

    const float inv0 = 1.f / lrow[0];
    const float inv1 = 1.f / lrow[1];
    const int row0 = q0 + m0 + g;
    __half* op0 = Og + base + (size_t)row0 * D_;
    __half* op1 = op0 + 8 * D_;
#pragma unroll
    for (int ni = 0; ni < 8; ni++) {
        int col = ni * 8 + 2 * tg;
        *(uint32_t*)(op0 + col) = pack_h2(o[ni][0] * inv0, o[ni][1] * inv0);
        *(uint32_t*)(op1 + col) = pack_h2(o[ni][2] * inv1, o[ni][3] * inv1);
    }
}

// ---------------------------------------------------------------------------
extern "C" void kernel_launch(void* const* d_in, const int* in_sizes, int n_in,
                              void* d_out, int out_size)
{
    const float* x  = (const float*)d_in[0];
    const float* Wq = (const float*)d_in[1];
    const float* Wk = (const float*)d_in[2];
    const float* Wv = (const float*)d_in[3];
    const float* Wo = (const float*)d_in[4];
    float* out = (float*)d_out;

    __half *q, *k, *v, *o, *xh, *wh;
    cudaGetSymbolAddress((void**)&q,  g_q);
    cudaGetSymbolAddress((void**)&k,  g_k);
    cudaGetSymbolAddress((void**)&v,  g_v);
    cudaGetSymbolAddress((void**)&o,  g_o);
    cudaGetSymbolAddress((void**)&xh, g_xh);
    cudaGetSymbolAddress((void**)&wh, g_wh);
    const size_t WSZ = (size_t)D_ * D_;

    static bool attr_set = false;
    if (!attr_set) {
        cudaFuncSetAttribute(flash_attn_h,
                             cudaFuncAttributeMaxDynamicSharedMemorySize, FA_SMEM_B);
        cudaFuncSetAttribute(gemm_h,
                             cudaFuncAttributeMaxDynamicSharedMemorySize, G_SMEM_B);
        attr_set = true;
    }

    cvt_h_kernel<<<dim3(1024, 1, 8), 256>>>(x, Wq, Wk, Wv, Wo);

    gemm_h<<<dim3(D_ / 128, MTOT / 128, 3), 256, G_SMEM_B>>>(
        xh, wh + 0 * WSZ, wh + 1 * WSZ, wh + 2 * WSZ, q, k, v, 1);

    flash_attn_h<<<dim3(S_ / 128, B_ * H_), 256, FA_SMEM_B>>>(q, k, v, o);

    gemm_h<<<dim3(D_ / 128, MTOT / 128, 1), 256, G_SMEM_B>>>(
        o, wh + 3 * WSZ, wh + 3 * WSZ, wh + 3 * WSZ, out, out, out, 0);
}